// round 1
// baseline (speedup 1.0000x reference)
#include <cuda_runtime.h>

#define NJ   32
#define TPB  128
#define OUTC 94
#define ROW  95   // padded smem row stride: gcd(95-64=31? -> (95t+c)%32=(31t+c)%32, conflict-free)

struct Q { float x, y, z, w; };
struct V { float x, y, z; };

__device__ __forceinline__ V vsub(V a, V b) { return {a.x - b.x, a.y - b.y, a.z - b.z}; }
__device__ __forceinline__ V vcross(V a, V b) {
    return {a.y * b.z - a.z * b.y,
            a.z * b.x - a.x * b.z,
            a.x * b.y - a.y * b.x};
}
__device__ __forceinline__ float vdot(V a, V b) { return a.x * b.x + a.y * b.y + a.z * b.z; }

// t + 2*(v x (v x t + w t))
__device__ __forceinline__ V qrot(Q q, V t) {
    V v{q.x, q.y, q.z};
    V u = vcross(v, t);
    u.x = fmaf(q.w, t.x, u.x);
    u.y = fmaf(q.w, t.y, u.y);
    u.z = fmaf(q.w, t.z, u.z);
    V c = vcross(v, u);
    return {fmaf(2.0f, c.x, t.x), fmaf(2.0f, c.y, t.y), fmaf(2.0f, c.z, t.z)};
}

__device__ __forceinline__ Q qmul(Q a, Q b) {
    Q r;
    r.w = a.w * b.w - a.x * b.x - a.y * b.y - a.z * b.z;
    r.x = a.w * b.x + b.w * a.x + a.y * b.z - a.z * b.y;
    r.y = a.w * b.y + b.w * a.y + a.z * b.x - a.x * b.z;
    r.z = a.w * b.z + b.w * a.z + a.x * b.y - a.y * b.x;
    return r;
}

__device__ __forceinline__ void se3_log(V t, Q q, V& rho, V& phi) {
    // quat_log with sign canonicalization
    float sgn = (q.w < 0.0f) ? -1.0f : 1.0f;
    float qx = q.x * sgn, qy = q.y * sgn, qz = q.z * sgn, qw = q.w * sgn;
    float nv2 = qx * qx + qy * qy + qz * qz;
    float nv = sqrtf(fmaxf(nv2, 1e-14f));
    float angle = 2.0f * atan2f(nv, qw);
    float wsafe = (fabsf(qw) > 1e-8f) ? qw : 1.0f;
    float scale = (nv < 1e-6f) ? __fdividef(2.0f, wsafe) : __fdividef(angle, nv);
    phi = {qx * scale, qy * scale, qz * scale};

    float th2 = vdot(phi, phi);
    float th = sqrtf(fmaxf(th2, 1e-14f));
    bool small = th < 1e-4f;
    float ths = small ? 1.0f : th;
    float sn = __sinf(ths);
    float cs = __cosf(ths);
    float big = __fdividef(1.0f - __fdividef(ths * sn, 2.0f * (1.0f - cs)), ths * ths);
    float a = small ? (1.0f / 12.0f + th2 * (1.0f / 720.0f)) : big;

    V pt = vcross(phi, t);
    V ppt = vcross(phi, pt);
    rho = {t.x - 0.5f * pt.x + a * ppt.x,
           t.y - 0.5f * pt.y + a * ppt.y,
           t.z - 0.5f * pt.z + a * ppt.z};
}

// log( inv(target) o actual ): pos = R(conj(tq)) * (at - tt), q = conj(tq) * aq
__device__ __forceinline__ void pose_err_log(const float* __restrict__ tp,
                                             V at, Q aq, V& rho, V& phi) {
    V tt{__ldg(tp + 0), __ldg(tp + 1), __ldg(tp + 2)};
    Q tq{__ldg(tp + 3), __ldg(tp + 4), __ldg(tp + 5), __ldg(tp + 6)};
    Q qi{-tq.x, -tq.y, -tq.z, tq.w};
    V pe = qrot(qi, vsub(at, tt));
    Q qe = qmul(qi, aq);
    se3_log(pe, qe, rho, phi);
}

__global__ void __launch_bounds__(TPB)
ik_residual_kernel(const float* __restrict__ cfg,
                   const float* __restrict__ base,
                   const float* __restrict__ tgt,       // [4,7]
                   const float* __restrict__ dbase,     // [7]
                   const float* __restrict__ rest,      // [32]
                   const float* __restrict__ joff,      // [32,7]
                   const float* __restrict__ jaxis,     // [32,3]
                   const float* __restrict__ jlo,       // [32]
                   const float* __restrict__ jup,       // [32]
                   float* __restrict__ out) {
    __shared__ float s[TPB * ROW];  // 48640 B

    const int t = threadIdx.x;
    const int b0 = blockIdx.x * TPB;

    // ---- stage base poses coalesced, read own 7 into regs ----
    {
        const float* gb = base + (size_t)b0 * 7;
        #pragma unroll
        for (int i = t; i < TPB * 7; i += TPB) s[i] = gb[i];
    }
    __syncthreads();
    float bp[7];
    #pragma unroll
    for (int i = 0; i < 7; i++) bp[i] = s[t * 7 + i];
    __syncthreads();  // base region will be overwritten by output staging

    // ---- load cfg row (vectorized, 8x LDG.128) ----
    const int b = b0 + t;
    float th[NJ];
    {
        const float4* c4 = (const float4*)(cfg + (size_t)b * NJ);
        #pragma unroll
        for (int i = 0; i < NJ / 4; i++) {
            float4 v = __ldg(c4 + i);
            th[4 * i + 0] = v.x; th[4 * i + 1] = v.y;
            th[4 * i + 2] = v.z; th[4 * i + 3] = v.w;
        }
    }

    float* row = s + t * ROW;

    // ---- forward kinematics chain ----
    V Tt{bp[0], bp[1], bp[2]};
    Q Tq{bp[3], bp[4], bp[5], bp[6]};

    #pragma unroll
    for (int j = 0; j < NJ; j++) {
        const float* o = joff + j * 7;
        V ot{__ldg(o + 0), __ldg(o + 1), __ldg(o + 2)};
        Q oq{__ldg(o + 3), __ldg(o + 4), __ldg(o + 5), __ldg(o + 6)};
        // T = compose(T, offset)
        V rt = qrot(Tq, ot);
        Tt.x += rt.x; Tt.y += rt.y; Tt.z += rt.z;
        Tq = qmul(Tq, oq);
        // joint rotation about axis
        float sh, ch;
        __sincosf(0.5f * th[j], &sh, &ch);
        const float* ax = jaxis + j * 3;
        Q jq{__ldg(ax + 0) * sh, __ldg(ax + 1) * sh, __ldg(ax + 2) * sh, ch};
        Tq = qmul(Tq, jq);

        if ((j & 7) == 7) {  // TARGET_LINKS = 8,16,24,32 -> after j = 7,15,23,31
            int k = j >> 3;
            V rho, phi;
            pose_err_log(tgt + k * 7, Tt, Tq, rho, phi);
            row[k * 6 + 0] = rho.x;          // POS_W * POSE_W = 1
            row[k * 6 + 1] = rho.y;
            row[k * 6 + 2] = rho.z;
            row[k * 6 + 3] = 0.5f * phi.x;   // ORI_W * POSE_W = 0.5
            row[k * 6 + 4] = 0.5f * phi.y;
            row[k * 6 + 5] = 0.5f * phi.z;
        }
    }

    // ---- joint limit + rest residuals ----
    #pragma unroll
    for (int j = 0; j < NJ; j++) {
        float c = th[j];
        float lim = fmaxf(c - __ldg(jup + j), 0.0f) + fminf(c - __ldg(jlo + j), 0.0f);
        row[24 + j] = lim * 10.0f;
        row[56 + j] = (c - __ldg(rest + j)) * 0.1f;
    }

    // ---- base residual ----
    {
        V rho, phi;
        V bt{bp[0], bp[1], bp[2]};
        Q bq{bp[3], bp[4], bp[5], bp[6]};
        pose_err_log(dbase, bt, bq, rho, phi);
        row[88] = rho.x * 5.0f;
        row[89] = rho.y * 5.0f;
        row[90] = rho.z * 5.0f;
        row[91] = phi.x * 5.0f;
        row[92] = phi.y * 5.0f;
        row[93] = phi.z * 5.0f;
    }

    __syncthreads();

    // ---- coalesced output flush ----
    float* go = out + (size_t)b0 * OUTC;
    #pragma unroll 4
    for (int e = t; e < TPB * OUTC; e += TPB) {
        int r = e / OUTC;           // constant division -> mul/shift
        int c = e - r * OUTC;
        go[e] = s[r * ROW + c];
    }
}

extern "C" void kernel_launch(void* const* d_in, const int* in_sizes, int n_in,
                              void* d_out, int out_size) {
    const float* cfg   = (const float*)d_in[0];
    const float* base  = (const float*)d_in[1];
    const float* tgt   = (const float*)d_in[2];
    const float* dbase = (const float*)d_in[3];
    const float* rest  = (const float*)d_in[4];
    const float* joff  = (const float*)d_in[5];
    const float* jaxis = (const float*)d_in[6];
    const float* jlo   = (const float*)d_in[7];
    const float* jup   = (const float*)d_in[8];
    float* out = (float*)d_out;

    int B = in_sizes[0] / NJ;       // 65536
    int nblocks = B / TPB;          // 512

    ik_residual_kernel<<<nblocks, TPB>>>(cfg, base, tgt, dbase, rest,
                                         joff, jaxis, jlo, jup, out);
}

// round 2
// speedup vs baseline: 1.1364x; 1.1364x over previous
#include <cuda_runtime.h>

#define NJ   32
#define TPB  128
#define OUTC 94

// ---- dynamic smem float offsets ----
#define S_OUT   0
#define S_BASE  (TPB * OUTC)          // 12032
#define S_TGT   (S_BASE + TPB * 7)    // 12928  (4 x 7)
#define S_DB    (S_TGT + 28)          // 12956  (7)
#define S_REST  (S_DB + 7)            // 12963  (32)
#define S_JLO   (S_REST + 32)         // 12995  (32)
#define S_JUP   (S_JLO + 32)          // 13027  (32)
#define S_JOFF  (S_JUP + 32)          // 13059  (32 x 7)
#define S_P     (S_JOFF + 224)        // 13283  (32 x 4)
#define S_TOTAL (S_P + 128)           // 13411 floats = 53644 B

struct Q { float x, y, z, w; };
struct V { float x, y, z; };

__device__ __forceinline__ V vcross(V a, V b) {
    return {a.y * b.z - a.z * b.y,
            a.z * b.x - a.x * b.z,
            a.x * b.y - a.y * b.x};
}

// t + 2*(v x (v x t + w t))
__device__ __forceinline__ V qrot(Q q, V t) {
    V v{q.x, q.y, q.z};
    V u = vcross(v, t);
    u.x = fmaf(q.w, t.x, u.x);
    u.y = fmaf(q.w, t.y, u.y);
    u.z = fmaf(q.w, t.z, u.z);
    V c = vcross(v, u);
    return {fmaf(2.0f, c.x, t.x), fmaf(2.0f, c.y, t.y), fmaf(2.0f, c.z, t.z)};
}

__device__ __forceinline__ Q qmul(Q a, Q b) {
    Q r;
    r.w = a.w * b.w - a.x * b.x - a.y * b.y - a.z * b.z;
    r.x = a.w * b.x + b.w * a.x + a.y * b.z - a.z * b.y;
    r.y = a.w * b.y + b.w * a.y + a.z * b.x - a.x * b.z;
    r.z = a.w * b.z + b.w * a.z + a.x * b.y - a.y * b.x;
    return r;
}

// atan2(y, x) for y >= 0, x >= 0, not both zero. 6-coeff minimax atan on [0,1].
__device__ __forceinline__ float atan2pos(float y, float x) {
    float mn = fminf(y, x), mx = fmaxf(y, x);
    float r  = __fdividef(mn, mx);
    float r2 = r * r;
    float p = fmaf(r2, -0.0117212f,  0.05265332f);
    p = fmaf(r2, p, -0.11643287f);
    p = fmaf(r2, p,  0.19354346f);
    p = fmaf(r2, p, -0.33262347f);
    p = fmaf(r2, p,  0.99997726f);
    float th = r * p;
    return (y > x) ? (1.57079632679489662f - th) : th;
}

// se3_log for UNIT quaternion q (product of unit quats): uses the identities
// |phi| = angle, sin(angle) = 2*nv*qw, 1 - cos(angle) = 2*nv^2.
__device__ __forceinline__ void se3_log(V t, Q q, V& rho, V& phi) {
    float sgn = (q.w < 0.0f) ? -1.0f : 1.0f;
    float qx = q.x * sgn, qy = q.y * sgn, qz = q.z * sgn, qw = q.w * sgn;
    float nv2 = qx * qx + qy * qy + qz * qz;
    float nv  = sqrtf(fmaxf(nv2, 1e-14f));
    float angle = 2.0f * atan2pos(nv, qw);
    float wsafe = (fabsf(qw) > 1e-8f) ? qw : 1.0f;
    float scale = (nv < 1e-6f) ? __fdividef(2.0f, wsafe) : __fdividef(angle, nv);
    phi = {qx * scale, qy * scale, qz * scale};

    float th  = angle;                 // == |phi| up to rounding
    float th2 = th * th;
    float abig = __fdividef(1.0f - 0.5f * scale * qw, th2);
    float a = (th < 1e-4f) ? (1.0f / 12.0f + th2 * (1.0f / 720.0f)) : abig;

    V pt  = vcross(phi, t);
    V ppt = vcross(phi, pt);
    rho = {t.x - 0.5f * pt.x + a * ppt.x,
           t.y - 0.5f * pt.y + a * ppt.y,
           t.z - 0.5f * pt.z + a * ppt.z};
}

// log( inv(target) o actual ), target pose (7 floats) read from smem
__device__ __forceinline__ void pose_err_log(const float* tp, V at, Q aq,
                                             V& rho, V& phi) {
    Q qi{-tp[3], -tp[4], -tp[5], tp[6]};
    V d{at.x - tp[0], at.y - tp[1], at.z - tp[2]};
    V pe = qrot(qi, d);
    Q qe = qmul(qi, aq);
    se3_log(pe, qe, rho, phi);
}

__global__ void __launch_bounds__(TPB, 4)
ik_residual_kernel(const float* __restrict__ cfg,
                   const float* __restrict__ base,
                   const float* __restrict__ tgt,
                   const float* __restrict__ dbase,
                   const float* __restrict__ rest,
                   const float* __restrict__ joff,
                   const float* __restrict__ jaxis,
                   const float* __restrict__ jlo,
                   const float* __restrict__ jup,
                   float* __restrict__ out) {
    extern __shared__ float s[];

    const int t  = threadIdx.x;
    const int b0 = blockIdx.x * TPB;

    // ---- stage everything into smem (one pass, one barrier) ----
    {
        const float* gb = base + (size_t)b0 * 7;
        #pragma unroll
        for (int i = t; i < TPB * 7; i += TPB) s[S_BASE + i] = gb[i];
        #pragma unroll
        for (int i = t; i < 224; i += TPB) s[S_JOFF + i] = __ldg(joff + i);
        if (t < 28) s[S_TGT + t] = __ldg(tgt + t);
        if (t < 7)  s[S_DB + t]  = __ldg(dbase + t);
        if (t < 32) {
            s[S_REST + t] = __ldg(rest + t);
            s[S_JLO + t]  = __ldg(jlo + t);
            s[S_JUP + t]  = __ldg(jup + t);
            // P_j = oq_j (x) [axis_j, 0]  (pure-quat right-multiply, constant)
            float ox = __ldg(joff + t * 7 + 3), oy = __ldg(joff + t * 7 + 4);
            float oz = __ldg(joff + t * 7 + 5), ow = __ldg(joff + t * 7 + 6);
            float ax = __ldg(jaxis + t * 3 + 0), ay = __ldg(jaxis + t * 3 + 1);
            float az = __ldg(jaxis + t * 3 + 2);
            s[S_P + t * 4 + 0] = ow * ax + oy * az - oz * ay;
            s[S_P + t * 4 + 1] = ow * ay + oz * ax - ox * az;
            s[S_P + t * 4 + 2] = ow * az + ox * ay - oy * ax;
            s[S_P + t * 4 + 3] = -(ox * ax + oy * ay + oz * az);
        }
    }
    __syncthreads();

    float bp[7];
    #pragma unroll
    for (int i = 0; i < 7; i++) bp[i] = s[S_BASE + t * 7 + i];

    const int b = b0 + t;
    float* row = s + S_OUT + t * OUTC;

    // ---- forward kinematics + inline limit/rest residuals ----
    V Tt{bp[0], bp[1], bp[2]};
    Q Tq{bp[3], bp[4], bp[5], bp[6]};

    const float4* c4 = (const float4*)(cfg + (size_t)b * NJ);
    float4 cbuf;

    #pragma unroll
    for (int j = 0; j < NJ; j++) {
        if ((j & 3) == 0) cbuf = __ldg(c4 + (j >> 2));
        float thj = ((j & 3) == 0) ? cbuf.x :
                    ((j & 3) == 1) ? cbuf.y :
                    ((j & 3) == 2) ? cbuf.z : cbuf.w;

        // limit / rest residuals
        float lim = fmaxf(thj - s[S_JUP + j], 0.0f) + fminf(thj - s[S_JLO + j], 0.0f);
        row[24 + j] = lim * 10.0f;
        row[56 + j] = (thj - s[S_REST + j]) * 0.1f;

        // T = compose(T, offset); Tq = Tq * (c*oq + s*P_j)
        const float* o = s + S_JOFF + j * 7;
        V ot{o[0], o[1], o[2]};
        Q oq{o[3], o[4], o[5], o[6]};
        V rt = qrot(Tq, ot);
        Tt.x += rt.x; Tt.y += rt.y; Tt.z += rt.z;

        float sh, ch;
        __sincosf(0.5f * thj, &sh, &ch);
        const float* pj = s + S_P + j * 4;
        Q M{ch * oq.x + sh * pj[0],
            ch * oq.y + sh * pj[1],
            ch * oq.z + sh * pj[2],
            ch * oq.w + sh * pj[3]};
        Tq = qmul(Tq, M);

        if ((j & 7) == 7) {   // TARGET_LINKS = 8,16,24,32
            int k = j >> 3;
            V rho, phi;
            pose_err_log(s + S_TGT + k * 7, Tt, Tq, rho, phi);
            row[k * 6 + 0] = rho.x;
            row[k * 6 + 1] = rho.y;
            row[k * 6 + 2] = rho.z;
            row[k * 6 + 3] = 0.5f * phi.x;
            row[k * 6 + 4] = 0.5f * phi.y;
            row[k * 6 + 5] = 0.5f * phi.z;
        }
    }

    // ---- base residual ----
    {
        V rho, phi;
        pose_err_log(s + S_DB, V{bp[0], bp[1], bp[2]}, Q{bp[3], bp[4], bp[5], bp[6]},
                     rho, phi);
        row[88] = rho.x * 5.0f;
        row[89] = rho.y * 5.0f;
        row[90] = rho.z * 5.0f;
        row[91] = phi.x * 5.0f;
        row[92] = phi.y * 5.0f;
        row[93] = phi.z * 5.0f;
    }

    __syncthreads();

    // ---- flat vectorized flush: smem layout == gmem layout ----
    {
        float4* go4 = (float4*)(out + (size_t)b0 * OUTC);
        const float4* s4 = (const float4*)(s + S_OUT);
        #pragma unroll
        for (int f = t; f < TPB * OUTC / 4; f += TPB) go4[f] = s4[f];
    }
}

extern "C" void kernel_launch(void* const* d_in, const int* in_sizes, int n_in,
                              void* d_out, int out_size) {
    const float* cfg   = (const float*)d_in[0];
    const float* base  = (const float*)d_in[1];
    const float* tgt   = (const float*)d_in[2];
    const float* dbase = (const float*)d_in[3];
    const float* rest  = (const float*)d_in[4];
    const float* joff  = (const float*)d_in[5];
    const float* jaxis = (const float*)d_in[6];
    const float* jlo   = (const float*)d_in[7];
    const float* jup   = (const float*)d_in[8];
    float* out = (float*)d_out;

    const int smem_bytes = S_TOTAL * sizeof(float);   // 53644
    cudaFuncSetAttribute(ik_residual_kernel,
                         cudaFuncAttributeMaxDynamicSharedMemorySize, smem_bytes);

    int B = in_sizes[0] / NJ;     // 65536
    int nblocks = B / TPB;        // 512

    ik_residual_kernel<<<nblocks, TPB, smem_bytes>>>(cfg, base, tgt, dbase, rest,
                                                     joff, jaxis, jlo, jup, out);
}